// round 1
// baseline (speedup 1.0000x reference)
#include <cuda_runtime.h>

// x: (256, 2048, 25, 2) fp32 -> 26,214,400 floats = 6,553,600 float4s.
// weights: (2048, 1) fp32, only weights[0] used (faithful-to-reference quirk).
// out[b,f,j,:] = j < 8 ? (x*c + y*s, -x*s + y*c) : (x, y), theta = weights[0].

static constexpr long long TOTAL_FLOATS = 256LL * 2048 * 25 * 2;  // 26,214,400
static constexpr int N4 = (int)(TOTAL_FLOATS / 4);                // 6,553,600

__global__ void __launch_bounds__(256) rigid_rot_kernel(
    const float4* __restrict__ in,
    const float* __restrict__ w,
    float4* __restrict__ out)
{
    int i = blockIdx.x * blockDim.x + threadIdx.x;
    if (i >= N4) return;

    float s, c;
    sincosf(__ldg(w), &s, &c);

    float4 v = in[i];

    // This float4 covers pairs p0 = 2i and p1 = 2i+1 (each pair = one joint's (x,y)).
    int p0 = 2 * i;
    int j0 = p0 % 25;
    int j1 = j0 + 1; if (j1 == 25) j1 = 0;

    if (j0 < 8) {
        float x = v.x, y = v.y;
        v.x = fmaf(x, c, y * s);
        v.y = fmaf(-x, s, y * c);
    }
    if (j1 < 8) {
        float x = v.z, y = v.w;
        v.z = fmaf(x, c, y * s);
        v.w = fmaf(-x, s, y * c);
    }

    out[i] = v;
}

extern "C" void kernel_launch(void* const* d_in, const int* in_sizes, int n_in,
                              void* d_out, int out_size)
{
    const float4* x = (const float4*)d_in[0];
    const float*  w = (const float*)d_in[1];
    float4* out = (float4*)d_out;

    int threads = 256;
    int blocks = (N4 + threads - 1) / threads;  // 25,600
    rigid_rot_kernel<<<blocks, threads>>>(x, w, out);
}